// round 15
// baseline (speedup 1.0000x reference)
#include <cuda_runtime.h>
#include <cuda_fp16.h>
#include <math.h>
#include <stdint.h>

// ---------------- problem constants ----------------
#define NB      64
#define CIN     64
#define TT      512
#define NN      32768
#define DD      128
#define EE      524288
#define ETOT    557056
#define EPSB    1e-5f

typedef unsigned long long ull;

// ---------------- device scratch ----------------
__device__ __align__(16) float g_xl[NN * DD];
__device__ __align__(16) float g_xr[NN * DD];
__device__ __align__(16) float g_gacc[NN * DD];
__device__ __align__(16) float g_y[NB * 512 * 128];
__device__ __align__(16) __half g_wfh[256 * 64];       // fused [W_l|W_r] as [j][c] fp16
__device__ __align__(16) float g_wcs[256];
__device__ __align__(16) __half g_wh[9 * 512 * 512];   // conv W [k][o][i] fp16
__device__ __align__(16) __half g_xh[NB * 128 * 512];  // [b][q][i] fp16
__device__ int g_deg[NN];
__device__ int g_rowptr[NN + 1];
__device__ int g_cursor[NN];
__device__ int g_csrc[ETOT];
__device__ int g_bsum[32];
__device__ float g_bn0sum[64], g_bn0sq[64];
__device__ float g_bn0s[64], g_bn0t[64];
__device__ float g_bn1sum[128], g_bn1sq[128];
__device__ float g_bn2sum[512], g_bn2sq[512];

// ---------------- host-side stream/event resources (created pre-main) ----------------
struct HxStreams {
    cudaStream_t s1;
    cudaEvent_t ev0, ev1, ev2, evA, evB;
    HxStreams() {
        cudaStreamCreateWithFlags(&s1, cudaStreamNonBlocking);
        cudaEventCreateWithFlags(&ev0, cudaEventDisableTiming);
        cudaEventCreateWithFlags(&ev1, cudaEventDisableTiming);
        cudaEventCreateWithFlags(&ev2, cudaEventDisableTiming);
        cudaEventCreateWithFlags(&evA, cudaEventDisableTiming);
        cudaEventCreateWithFlags(&evB, cudaEventDisableTiming);
    }
};
static HxStreams g_hx;

// ---------------- helpers ----------------
__device__ __forceinline__ uint32_t smem_u32(const void* p) {
    uint32_t a;
    asm("{ .reg .u64 t; cvta.to.shared.u64 t, %1; cvt.u32.u64 %0, t; }" : "=r"(a) : "l"(p));
    return a;
}
__device__ __forceinline__ void cpa16(uint32_t dst, const void* src) {
    asm volatile("cp.async.cg.shared.global [%0], [%1], 16;" :: "r"(dst), "l"(src));
}
__device__ __forceinline__ void ldsm4(uint32_t* r, uint32_t addr) {
    asm volatile("ldmatrix.sync.aligned.m8n8.x4.shared.b16 {%0,%1,%2,%3}, [%4];"
                 : "=r"(r[0]), "=r"(r[1]), "=r"(r[2]), "=r"(r[3]) : "r"(addr));
}
__device__ __forceinline__ void mma16816h(float* d, const uint32_t* a, uint32_t b0, uint32_t b1) {
    asm volatile("mma.sync.aligned.m16n8k16.row.col.f32.f16.f16.f32 "
                 "{%0,%1,%2,%3}, {%4,%5,%6,%7}, {%8,%9}, {%0,%1,%2,%3};"
                 : "+f"(d[0]), "+f"(d[1]), "+f"(d[2]), "+f"(d[3])
                 : "r"(a[0]), "r"(a[1]), "r"(a[2]), "r"(a[3]), "r"(b0), "r"(b1));
}

// ---------------- branch A init: deg=1 ----------------
__global__ void k_initA() {
    int i = blockIdx.x * 1024 + threadIdx.x;
    g_deg[i] = 1;
}

// ---------------- branch B init: zero stat partials ----------------
__global__ void k_initB() {
    int i = threadIdx.x;
    if (i < 512) { g_bn2sum[i] = 0.f; g_bn2sq[i] = 0.f; }
    if (i < 128) { g_bn1sum[i] = 0.f; g_bn1sq[i] = 0.f; }
    if (i < 64)  { g_bn0sum[i] = 0.f; g_bn0sq[i] = 0.f; }
}

__global__ void k_hist(const int* __restrict__ ei) {
    int e = blockIdx.x * 1024 + threadIdx.x;
    if (e < EE) atomicAdd(&g_deg[ei[EE + e]], 1);
}

// ---------------- BN0 partial stats ----------------
__global__ void k_bn0p(const float* __restrict__ x) {
    int c = blockIdx.x >> 3;
    int sl = blockIdx.x & 7;
    const float4* base = (const float4*)(x + (size_t)(sl * 8) * 32768 + c * 512);
    int t = threadIdx.x;
    float s = 0.f, q = 0.f;
#pragma unroll
    for (int j = 0; j < 4; j++) {
        int u = t + j * 256;
        int r = u >> 7, col = u & 127;
        float4 v = base[(size_t)r * 8192 + col];
        s += v.x + v.y + v.z + v.w;
        q += v.x * v.x + v.y * v.y + v.z * v.z + v.w * v.w;
    }
    __shared__ float rs[256], rq[256];
    rs[t] = s; rq[t] = q;
    __syncthreads();
    for (int st = 128; st > 0; st >>= 1) {
        if (t < st) { rs[t] += rs[t + st]; rq[t] += rq[t + st]; }
        __syncthreads();
    }
    if (t == 0) { atomicAdd(&g_bn0sum[c], rs[0]); atomicAdd(&g_bn0sq[c], rq[0]); }
}

// ---------------- parallel scan ----------------
__global__ void __launch_bounds__(1024) k_scanA() {
    __shared__ int wsum[32];
    int t = threadIdx.x;
    int n = blockIdx.x * 1024 + t;
    int lane = t & 31, w = t >> 5;
    int d = g_deg[n];
    int incl = d;
#pragma unroll
    for (int off = 1; off < 32; off <<= 1) {
        int v = __shfl_up_sync(0xffffffffu, incl, off);
        if (lane >= off) incl += v;
    }
    if (lane == 31) wsum[w] = incl;
    __syncthreads();
    if (w == 0) {
        int v = wsum[lane];
        int wi = v;
#pragma unroll
        for (int off = 1; off < 32; off <<= 1) {
            int u = __shfl_up_sync(0xffffffffu, wi, off);
            if (lane >= off) wi += u;
        }
        wsum[lane] = wi - v;
        if (lane == 31) g_bsum[blockIdx.x] = wi;
    }
    __syncthreads();
    g_rowptr[n] = incl - d + wsum[w];
}

__global__ void __launch_bounds__(1024) k_scanC() {
    __shared__ int boff;
    int t = threadIdx.x;
    if (t < 32) {
        int v = g_bsum[t];
        int s = v;
#pragma unroll
        for (int off = 1; off < 32; off <<= 1) {
            int u = __shfl_up_sync(0xffffffffu, s, off);
            if (t >= off) s += u;
        }
        if (t == (int)blockIdx.x) boff = s - v;
        if (t == 31 && blockIdx.x == 31) g_rowptr[NN] = s;
    }
    __syncthreads();
    int n = blockIdx.x * 1024 + t;
    int run = g_rowptr[n] + boff;
    g_rowptr[n] = run;
    g_cursor[n] = run + 1;
    g_csrc[run] = n;
}

__global__ void k_scatter(const int* __restrict__ ei) {
    int e = blockIdx.x * 1024 + threadIdx.x;
    if (e < EE) {
        int d = ei[EE + e];
        int pos = atomicAdd(&g_cursor[d], 1);
        g_csrc[pos] = ei[e];
    }
}

// ---------------- fuse W_l|W_r (fp16 K-major) + colsums + finalize BN0 ----------------
__global__ void k_fusew(const float* __restrict__ wl, const float* __restrict__ wr,
                        const float* __restrict__ g0, const float* __restrict__ b0) {
    int j = threadIdx.x;
    if (j < 64) {
        float m = g_bn0sum[j] * (1.f / 32768.f);
        float var = g_bn0sq[j] * (1.f / 32768.f) - m * m;
        float a = g0[j] * rsqrtf(var + EPSB);
        g_bn0s[j] = a;
        g_bn0t[j] = b0[j] - m * a;
    }
    float cs = 0.f;
    for (int c = 0; c < 64; c++) {
        float w = (j < 128) ? wl[c * 128 + j] : wr[c * 128 + (j - 128)];
        g_wfh[j * 64 + c] = __float2half_rn(w);
        cs += w;
    }
    g_wcs[j] = cs;
}

// ---------------- GEMM1 via HMMA ----------------
__global__ void __launch_bounds__(256, 1) k_gemm1h(const float* __restrict__ x) {
    extern __shared__ char sm[];
    uint32_t sb = smem_u32(sm);
    const uint32_t Ab = sb;
    const uint32_t Bb = sb + 16384;
    int tid = threadIdx.x;
    int blk = blockIdx.x;

#pragma unroll
    for (int it = 0; it < 8; it++) {
        int ch = tid + it * 256;
        int j = ch >> 3, c = ch & 7;
        cpa16(Bb + j * 128 + ((c * 16) ^ ((j & 7) * 16)), g_wfh + j * 64 + c * 8);
    }
    asm volatile("cp.async.commit_group;" ::: "memory");

    const float4* xg = (const float4*)(x + (size_t)blk * 128 * 64);
#pragma unroll
    for (int it = 0; it < 4; it++) {
        int ch = tid + it * 256;
        int r = ch >> 3, c = ch & 7;
        float4 f0 = xg[r * 16 + c * 2];
        float4 f1 = xg[r * 16 + c * 2 + 1];
        __half2 h0 = __float22half2_rn(make_float2(f0.x, f0.y));
        __half2 h1 = __float22half2_rn(make_float2(f0.z, f0.w));
        __half2 h2 = __float22half2_rn(make_float2(f1.x, f1.y));
        __half2 h3 = __float22half2_rn(make_float2(f1.z, f1.w));
        uint4 u;
        u.x = *(uint32_t*)&h0; u.y = *(uint32_t*)&h1;
        u.z = *(uint32_t*)&h2; u.w = *(uint32_t*)&h3;
        *(uint4*)(sm + r * 128 + ((c * 16) ^ ((r & 7) * 16))) = u;
    }
    asm volatile("cp.async.wait_group 0;" ::: "memory");
    __syncthreads();

    int lane = tid & 31, wid = tid >> 5;
    int wm = wid & 3;
    int wn = wid >> 2;
    float acc[2][16][4];
#pragma unroll
    for (int mt = 0; mt < 2; mt++)
#pragma unroll
        for (int nt = 0; nt < 16; nt++)
#pragma unroll
            for (int u = 0; u < 4; u++) acc[mt][nt][u] = 0.f;

    const int arow = wm * 32 + (lane & 15);
    const int aswz = (arow & 7) * 16;
    const int brow = wn * 128 + (lane & 15);
    const int bswz = (brow & 7) * 16;

#pragma unroll
    for (int k = 0; k < 4; k++) {
        const int c16 = k * 2 + (lane >> 4);
        uint32_t afr[2][4];
#pragma unroll
        for (int mt = 0; mt < 2; mt++)
            ldsm4(afr[mt], Ab + (arow + mt * 16) * 128 + ((c16 * 16) ^ aswz));
        uint32_t bfr[8][4];
#pragma unroll
        for (int n16 = 0; n16 < 8; n16++)
            ldsm4(bfr[n16], Bb + (brow + n16 * 16) * 128 + ((c16 * 16) ^ bswz));
#pragma unroll
        for (int mt = 0; mt < 2; mt++)
#pragma unroll
            for (int nt = 0; nt < 16; nt++) {
                const int n16 = nt >> 1, odd = nt & 1;
                mma16816h(acc[mt][nt], afr[mt], bfr[n16][odd], bfr[n16][odd + 2]);
            }
    }

    float* dst = (wn == 0) ? g_xl : g_xr;
#pragma unroll
    for (int mt = 0; mt < 2; mt++) {
        int row0 = blk * 128 + wm * 32 + mt * 16 + (lane >> 2);
        int row1 = row0 + 8;
        int cin0 = (row0 >> 3) & 63, cin1 = (row1 >> 3) & 63;
        float s0 = g_bn0s[cin0], t0 = g_bn0t[cin0];
        float s1 = g_bn0s[cin1], t1 = g_bn0t[cin1];
#pragma unroll
        for (int nt = 0; nt < 16; nt++) {
            int j = wn * 128 + nt * 8 + (lane & 3) * 2;
            float2 wc = *(const float2*)&g_wcs[j];
            int jj = j & 127;
            float2 v0, v1;
            v0.x = s0 * acc[mt][nt][0] + t0 * wc.x;
            v0.y = s0 * acc[mt][nt][1] + t0 * wc.y;
            v1.x = s1 * acc[mt][nt][2] + t1 * wc.x;
            v1.y = s1 * acc[mt][nt][3] + t1 * wc.y;
            *(float2*)&dst[(size_t)row0 * 128 + jj] = v0;
            *(float2*)&dst[(size_t)row1 * 128 + jj] = v1;
        }
    }
}

// ---------------- GATv2 gather (unroll x8) + fused BN1 stats ----------------
#define GAT_EDGE(AV) do { \
    float hx = AV.x + r.x; hx = fmaxf(hx, 0.2f * hx); \
    float hy = AV.y + r.y; hy = fmaxf(hy, 0.2f * hy); \
    float hz = AV.z + r.z; hz = fmaxf(hz, 0.2f * hz); \
    float hw = AV.w + r.w; hw = fmaxf(hw, 0.2f * hw); \
    float d = hx * av.x + hy * av.y + hz * av.z + hw * av.w; \
    d += __shfl_xor_sync(0xffffffffu, d, 8); \
    d += __shfl_xor_sync(0xffffffffu, d, 4); \
    d += __shfl_xor_sync(0xffffffffu, d, 2); \
    d += __shfl_xor_sync(0xffffffffu, d, 1); \
    float e = __expf(d); \
    z += e; \
    acc.x += e * AV.x; acc.y += e * AV.y; \
    acc.z += e * AV.z; acc.w += e * AV.w; \
} while (0)

__global__ void __launch_bounds__(256) k_gat(const float* __restrict__ att) {
    __shared__ float ssum[128], ssq[128];
    int tid = threadIdx.x;
    if (tid < 128) { ssum[tid] = 0.f; ssq[tid] = 0.f; }
    __syncthreads();
    int n = blockIdx.x * 8 + (tid >> 5);
    int lane = tid & 31;
    int row = g_rowptr[n];
    int end = g_rowptr[n + 1];
    float4 r = *(const float4*)(g_xr + (size_t)n * 128 + lane * 4);
    float4 av = *(const float4*)(att + lane * 4);
    float4 acc = make_float4(0.f, 0.f, 0.f, 0.f);
    float z = 0.f;
    for (int base = row; base < end; base += 32) {
        int m = end - base;
        if (m > 32) m = 32;
        int s = (lane < m) ? g_csrc[base + lane] : 0;
        int j = 0;
        for (; j + 8 <= m; j += 8) {
            int s0 = __shfl_sync(0xffffffffu, s, j);
            int s1 = __shfl_sync(0xffffffffu, s, j + 1);
            int s2 = __shfl_sync(0xffffffffu, s, j + 2);
            int s3 = __shfl_sync(0xffffffffu, s, j + 3);
            int s4 = __shfl_sync(0xffffffffu, s, j + 4);
            int s5 = __shfl_sync(0xffffffffu, s, j + 5);
            int s6 = __shfl_sync(0xffffffffu, s, j + 6);
            int s7 = __shfl_sync(0xffffffffu, s, j + 7);
            float4 a0 = *(const float4*)(g_xl + (size_t)s0 * 128 + lane * 4);
            float4 a1 = *(const float4*)(g_xl + (size_t)s1 * 128 + lane * 4);
            float4 a2 = *(const float4*)(g_xl + (size_t)s2 * 128 + lane * 4);
            float4 a3 = *(const float4*)(g_xl + (size_t)s3 * 128 + lane * 4);
            float4 a4 = *(const float4*)(g_xl + (size_t)s4 * 128 + lane * 4);
            float4 a5 = *(const float4*)(g_xl + (size_t)s5 * 128 + lane * 4);
            float4 a6 = *(const float4*)(g_xl + (size_t)s6 * 128 + lane * 4);
            float4 a7 = *(const float4*)(g_xl + (size_t)s7 * 128 + lane * 4);
            GAT_EDGE(a0); GAT_EDGE(a1); GAT_EDGE(a2); GAT_EDGE(a3);
            GAT_EDGE(a4); GAT_EDGE(a5); GAT_EDGE(a6); GAT_EDGE(a7);
        }
        for (; j < m; j++) {
            int s0 = __shfl_sync(0xffffffffu, s, j);
            float4 a0 = *(const float4*)(g_xl + (size_t)s0 * 128 + lane * 4);
            GAT_EDGE(a0);
        }
    }
    float inv = 1.f / z;
    float4 o = make_float4(acc.x * inv, acc.y * inv, acc.z * inv, acc.w * inv);
    *(float4*)(g_gacc + (size_t)n * 128 + lane * 4) = o;
    atomicAdd(&ssum[lane * 4 + 0], o.x);
    atomicAdd(&ssum[lane * 4 + 1], o.y);
    atomicAdd(&ssum[lane * 4 + 2], o.z);
    atomicAdd(&ssum[lane * 4 + 3], o.w);
    atomicAdd(&ssq[lane * 4 + 0], o.x * o.x);
    atomicAdd(&ssq[lane * 4 + 1], o.y * o.y);
    atomicAdd(&ssq[lane * 4 + 2], o.z * o.z);
    atomicAdd(&ssq[lane * 4 + 3], o.w * o.w);
    __syncthreads();
    if (tid < 128) {
        atomicAdd(&g_bn1sum[tid], ssum[tid]);
        atomicAdd(&g_bn1sq[tid], ssq[tid]);
    }
}

// ---------------- fused: relu(BN1) -> out + fp16 (half-batch, base offset) ----------------
__global__ void __launch_bounds__(1024) k_xn1s(float* __restrict__ out,
                                               const float* __restrict__ g1,
                                               const float* __restrict__ b1,
                                               int base) {
    __shared__ float sa[128], sc[128];
    int tid = threadIdx.x;
    if (tid < 128) {
        float m = g_bn1sum[tid] * (1.f / 32768.f);
        float var = g_bn1sq[tid] * (1.f / 32768.f) - m * m;
        float a = g1[tid] * rsqrtf(var + EPSB);
        sa[tid] = a;
        sc[tid] = b1[tid] - m * a;
    }
    __syncthreads();
    int i = base + blockIdx.x * 1024 + tid;
    int j = tid & 127;
    float v = g_gacc[i] * sa[j] + sc[j];
    v = fmaxf(v, 0.f);
    out[i] = v;
    g_xh[i] = __float2half_rn(v);
}

// ---------------- conv weight fp16 ----------------
__global__ void k_whalf(const float* __restrict__ w) {
    int idx = blockIdx.x * 256 + threadIdx.x;   // [k][o][i]
    int i = idx & 511;
    int o = (idx >> 9) & 511;
    int k = idx >> 18;
    g_wh[idx] = __float2half_rn(w[(o * 512 + i) * 9 + k]);
}

// ---------------- conv via mma.sync fp16, 2 batches per CTA + BN2 stats ----------------
#define W_STAGE 16384
#define X_BASE  49152
#define X_BUF   34816

__device__ __forceinline__ void fillW(uint32_t sb, int st, int t, int o0, int tid) {
    int kk = t % 9;
    int i0 = (t / 9) * 64;
#pragma unroll
    for (int j = 0; j < 4; j++) {
        int ch = tid + j * 256;
        int r = ch >> 3;
        int c = ch & 7;
        uint32_t dst = sb + st * W_STAGE + r * 128 + ((c * 16) ^ ((r & 7) * 16));
        const __half* src = g_wh + (size_t)(kk * 512 + o0 + r) * 512 + i0 + c * 8;
        cpa16(dst, src);
    }
}

__device__ __forceinline__ void fillX(char* cs, uint32_t sb, int jch, int b0, int tid) {
    int buf = jch & 1;
    int i0 = jch * 64;
#pragma unroll
    for (int jj = 0; jj < 9; jj++) {
        int ch = tid + jj * 256;
        if (ch < 2176) {
            int h = (ch >= 1088) ? 1 : 0;
            int ca = ch - h * 1088;
            int r = ca >> 3;
            int c = ca & 7;
            uint32_t rel = X_BASE + buf * X_BUF + h * 17408 + r * 128 + ((c * 16) ^ ((r & 7) * 16));
            int q = r - 4;
            if ((unsigned)q < 128u) {
                const __half* src = g_xh + (size_t)((b0 + h) * 128 + q) * 512 + i0 + c * 8;
                cpa16(sb + rel, src);
            } else {
                *(uint4*)(cs + rel) = make_uint4(0u, 0u, 0u, 0u);
            }
        }
    }
}

__global__ void __launch_bounds__(256, 1) k_conv_hmma(int bbase) {
    extern __shared__ char cs[];
    uint32_t sb = smem_u32(cs);
    const int tid = threadIdx.x;
    const int lane = tid & 31;
    const int wid = tid >> 5;
    const int wm = wid & 3;
    const int wn = wid >> 2;
    const int b0 = bbase + blockIdx.x * 2;
    const int o0 = blockIdx.y * 128;

    float acc[2][16][4];
#pragma unroll
    for (int mt = 0; mt < 2; mt++)
#pragma unroll
        for (int nt = 0; nt < 16; nt++)
#pragma unroll
            for (int u = 0; u < 4; u++) acc[mt][nt][u] = 0.f;

    fillW(sb, 0, 0, o0, tid);
    fillX(cs, sb, 0, b0, tid);
    asm volatile("cp.async.commit_group;" ::: "memory");
    fillW(sb, 1, 1, o0, tid);
    asm volatile("cp.async.commit_group;" ::: "memory");
    fillW(sb, 2, 2, o0, tid);
    asm volatile("cp.async.commit_group;" ::: "memory");

    const int arow = wm * 32 + (lane & 15);
    const int aswz = (arow & 7) * 16;
    const int brow0 = lane & 15;

    for (int t = 0; t < 72; t++) {
        if (t < 70)       asm volatile("cp.async.wait_group 2;" ::: "memory");
        else if (t == 70) asm volatile("cp.async.wait_group 1;" ::: "memory");
        else              asm volatile("cp.async.wait_group 0;" ::: "memory");
        __syncthreads();

        const int st = t % 3;
        const int kk = t % 9;
        const int xb = (t / 9) & 1;
        const uint32_t wbase = sb + st * W_STAGE;
        const uint32_t xbase = sb + X_BASE + xb * X_BUF + wn * 17408;
        const int brow = brow0 + kk;
        const int bswz = (brow & 7) * 16;

#pragma unroll
        for (int s = 0; s < 4; s++) {
            const int c16 = s * 2 + (lane >> 4);
            uint32_t afr[2][4];
#pragma unroll
            for (int mt = 0; mt < 2; mt++) {
                uint32_t addr = wbase + mt * 2048 + arow * 128 + ((c16 * 16) ^ aswz);
                ldsm4(afr[mt], addr);
            }
            uint32_t bfr[8][4];
#pragma unroll
            for (int n16 = 0; n16 < 8; n16++) {
                uint32_t addr = xbase + (brow + n16 * 16) * 128 + ((c16 * 16) ^ bswz);
                ldsm4(bfr[n16], addr);
            }
#pragma unroll
            for (int mt = 0; mt < 2; mt++)
#pragma unroll
                for (int nt = 0; nt < 16; nt++) {
                    const int n16 = nt >> 1, odd = nt & 1;
                    mma16816h(acc[mt][nt], afr[mt], bfr[n16][odd], bfr[n16][odd + 2]);
                }
        }
        __syncthreads();

        const int tf = t + 3;
        if (tf < 72) {
            fillW(sb, tf % 3, tf, o0, tid);
            if (tf % 9 == 0) fillX(cs, sb, tf / 9, b0, tid);
            asm volatile("cp.async.commit_group;" ::: "memory");
        }
    }

    const int b = b0 + wn;
#pragma unroll
    for (int mt = 0; mt < 2; mt++) {
        float slo = 0.f, qlo = 0.f, shi = 0.f, qhi = 0.f;
#pragma unroll
        for (int nt = 0; nt < 16; nt++) {
            int o = o0 + wm * 32 + mt * 16 + (lane >> 2);
            int p = nt * 8 + (lane & 3) * 2;
            float2 v0 = make_float2(acc[mt][nt][0], acc[mt][nt][1]);
            float2 v1 = make_float2(acc[mt][nt][2], acc[mt][nt][3]);
            *(float2*)&g_y[((size_t)b * 512 + o) * 128 + p] = v0;
            *(float2*)&g_y[((size_t)b * 512 + o + 8) * 128 + p] = v1;
            slo += v0.x + v0.y; qlo += v0.x * v0.x + v0.y * v0.y;
            shi += v1.x + v1.y; qhi += v1.x * v1.x + v1.y * v1.y;
        }
#pragma unroll
        for (int m = 1; m <= 2; m <<= 1) {
            slo += __shfl_xor_sync(0xffffffffu, slo, m);
            qlo += __shfl_xor_sync(0xffffffffu, qlo, m);
            shi += __shfl_xor_sync(0xffffffffu, shi, m);
            qhi += __shfl_xor_sync(0xffffffffu, qhi, m);
        }
        if ((lane & 3) == 0) {
            int o = o0 + wm * 32 + mt * 16 + (lane >> 2);
            atomicAdd(&g_bn2sum[o], slo);
            atomicAdd(&g_bn2sq[o], qlo);
            atomicAdd(&g_bn2sum[o + 8], shi);
            atomicAdd(&g_bn2sq[o + 8], qhi);
        }
    }
}

// ---------------- final (inline BN2 coefficients) ----------------
__global__ void k_final(float* __restrict__ out,
                        const float* __restrict__ g2, const float* __restrict__ b2) {
    __shared__ float sh[32][33];
    __shared__ float sa[32], sc[32];
    int bb = blockIdx.z;
    int o0 = blockIdx.y * 32;
    int p0 = blockIdx.x * 32;
    int tid = threadIdx.x;
    if (tid < 32) {
        int o = o0 + tid;
        float m = g_bn2sum[o] * (1.f / 8192.f);
        float var = g_bn2sq[o] * (1.f / 8192.f) - m * m;
        float a = g2[o] * rsqrtf(var + EPSB);
        sa[tid] = a;
        sc[tid] = b2[o] - m * a;
    }
    __syncthreads();
    for (int t = tid; t < 1024; t += 256) {
        int r = t >> 5, c = t & 31;
        int o = o0 + r;
        float v = g_y[(bb * 512 + o) * 128 + p0 + c];
        v = v * sa[r] + sc[r];
        sh[r][c] = fmaxf(v, 0.f);
    }
    __syncthreads();
    for (int t = tid; t < 1024; t += 256) {
        int r = t >> 5, c = t & 31;
        int d = p0 + r, tt = o0 + c;
        int idx = bb * 65536 + d * 512 + tt;
        out[idx] += sh[c][r];
    }
}

// ---------------- launch ----------------
extern "C" void kernel_launch(void* const* d_in, const int* in_sizes, int n_in,
                              void* d_out, int out_size) {
    const float* x     = (const float*)d_in[0];
    const int*   ei    = (const int*)d_in[1];
    const float* bn0g  = (const float*)d_in[2];
    const float* bn0b  = (const float*)d_in[3];
    const float* wl    = (const float*)d_in[4];
    const float* wr    = (const float*)d_in[5];
    const float* att   = (const float*)d_in[6];
    const float* bn1g  = (const float*)d_in[8];
    const float* bn1b  = (const float*)d_in[9];
    const float* convw = (const float*)d_in[10];
    const float* bn2g  = (const float*)d_in[12];
    const float* bn2b  = (const float*)d_in[13];
    float* out = (float*)d_out;

    cudaFuncSetAttribute(k_gemm1h, cudaFuncAttributeMaxDynamicSharedMemorySize, 49152);
    cudaFuncSetAttribute(k_conv_hmma, cudaFuncAttributeMaxDynamicSharedMemorySize, 118784);

    // fork: side stream s1 runs the feature track
    cudaEventRecord(g_hx.ev0, 0);
    cudaStreamWaitEvent(g_hx.s1, g_hx.ev0, 0);

    // branch B (s1)
    k_initB<<<1, 1024, 0, g_hx.s1>>>();
    k_bn0p<<<512, 256, 0, g_hx.s1>>>(x);
    k_fusew<<<1, 256, 0, g_hx.s1>>>(wl, wr, bn0g, bn0b);
    k_gemm1h<<<256, 256, 49152, g_hx.s1>>>(x);
    cudaEventRecord(g_hx.ev1, g_hx.s1);
    k_whalf<<<9216, 256, 0, g_hx.s1>>>(convw);
    cudaEventRecord(g_hx.ev2, g_hx.s1);

    // branch A (capture stream): CSR build
    k_initA<<<32, 1024>>>();
    k_hist<<<512, 1024>>>(ei);
    k_scanA<<<32, 1024>>>();
    k_scanC<<<32, 1024>>>();
    k_scatter<<<512, 1024>>>(ei);

    // join 1: gat needs gemm1 (xl/xr) + scatter (csrc)
    cudaStreamWaitEvent(0, g_hx.ev1, 0);
    k_gat<<<4096, 256>>>(att);

    // xn1s half 0 (batches 0-31) -> evA -> conv half 0 on s1
    k_xn1s<<<2048, 1024>>>(out, bn1g, bn1b, 0);
    cudaEventRecord(g_hx.evA, 0);
    cudaStreamWaitEvent(g_hx.s1, g_hx.evA, 0);           // s1 already past whalf
    k_conv_hmma<<<dim3(16, 4), 256, 118784, g_hx.s1>>>(0);
    cudaEventRecord(g_hx.evB, g_hx.s1);

    // xn1s half 1 + conv half 1 on capture stream (overlaps conv half 0)
    k_xn1s<<<2048, 1024>>>(out, bn1g, bn1b, 2097152);
    cudaStreamWaitEvent(0, g_hx.ev2, 0);
    k_conv_hmma<<<dim3(16, 4), 256, 118784>>>(32);

    // final waits both conv halves
    cudaStreamWaitEvent(0, g_hx.evB, 0);
    k_final<<<dim3(4, 16, 64), 256>>>(out, bn2g, bn2b);
}

// round 16
// speedup vs baseline: 1.0197x; 1.0197x over previous
#include <cuda_runtime.h>
#include <cuda_fp16.h>
#include <math.h>
#include <stdint.h>

// ---------------- problem constants ----------------
#define NB      64
#define CIN     64
#define TT      512
#define NN      32768
#define DD      128
#define EE      524288
#define ETOT    557056
#define EPSB    1e-5f

typedef unsigned long long ull;

// ---------------- device scratch ----------------
__device__ __align__(16) float g_xl[NN * DD];
__device__ __align__(16) float g_xr[NN * DD];
__device__ __align__(16) float g_gacc[NN * DD];
__device__ __align__(16) float g_y[NB * 512 * 128];
__device__ __align__(16) __half g_wfh[256 * 64];       // fused [W_l|W_r] as [j][c] fp16
__device__ __align__(16) float g_wcs[256];
__device__ __align__(16) __half g_wh[9 * 512 * 512];   // conv W [k][o][i] fp16
__device__ __align__(16) __half g_xh[NB * 128 * 512];  // [b][q][i] fp16
__device__ int g_deg[NN];
__device__ int g_rowptr[NN + 1];
__device__ int g_cursor[NN];
__device__ int g_csrc[ETOT];
__device__ int g_bsum[32];
__device__ float g_bn0sum[64], g_bn0sq[64];
__device__ float g_bn0s[64], g_bn0t[64];
__device__ float g_bn1sum[128], g_bn1sq[128];
__device__ float g_bn2sum[512], g_bn2sq[512];

// ---------------- host-side stream/event resources (created pre-main) ----------------
struct HxStreams {
    cudaStream_t s1;
    cudaEvent_t ev0, ev1, ev2;
    HxStreams() {
        cudaStreamCreateWithFlags(&s1, cudaStreamNonBlocking);
        cudaEventCreateWithFlags(&ev0, cudaEventDisableTiming);
        cudaEventCreateWithFlags(&ev1, cudaEventDisableTiming);
        cudaEventCreateWithFlags(&ev2, cudaEventDisableTiming);
    }
};
static HxStreams g_hx;

// ---------------- helpers ----------------
__device__ __forceinline__ uint32_t smem_u32(const void* p) {
    uint32_t a;
    asm("{ .reg .u64 t; cvta.to.shared.u64 t, %1; cvt.u32.u64 %0, t; }" : "=r"(a) : "l"(p));
    return a;
}
__device__ __forceinline__ void cpa16(uint32_t dst, const void* src) {
    asm volatile("cp.async.cg.shared.global [%0], [%1], 16;" :: "r"(dst), "l"(src));
}
__device__ __forceinline__ void ldsm4(uint32_t* r, uint32_t addr) {
    asm volatile("ldmatrix.sync.aligned.m8n8.x4.shared.b16 {%0,%1,%2,%3}, [%4];"
                 : "=r"(r[0]), "=r"(r[1]), "=r"(r[2]), "=r"(r[3]) : "r"(addr));
}
__device__ __forceinline__ void mma16816h(float* d, const uint32_t* a, uint32_t b0, uint32_t b1) {
    asm volatile("mma.sync.aligned.m16n8k16.row.col.f32.f16.f16.f32 "
                 "{%0,%1,%2,%3}, {%4,%5,%6,%7}, {%8,%9}, {%0,%1,%2,%3};"
                 : "+f"(d[0]), "+f"(d[1]), "+f"(d[2]), "+f"(d[3])
                 : "r"(a[0]), "r"(a[1]), "r"(a[2]), "r"(a[3]), "r"(b0), "r"(b1));
}

// ---------------- branch A init: deg=1 ----------------
__global__ void k_initA() {
    int i = blockIdx.x * 1024 + threadIdx.x;
    g_deg[i] = 1;
}

// ---------------- branch B init: zero stat partials ----------------
__global__ void k_initB() {
    int i = threadIdx.x;
    if (i < 512) { g_bn2sum[i] = 0.f; g_bn2sq[i] = 0.f; }
    if (i < 128) { g_bn1sum[i] = 0.f; g_bn1sq[i] = 0.f; }
    if (i < 64)  { g_bn0sum[i] = 0.f; g_bn0sq[i] = 0.f; }
}

__global__ void k_hist(const int* __restrict__ ei) {
    int e = blockIdx.x * 1024 + threadIdx.x;
    if (e < EE) atomicAdd(&g_deg[ei[EE + e]], 1);
}

// ---------------- BN0 partial stats ----------------
__global__ void k_bn0p(const float* __restrict__ x) {
    int c = blockIdx.x >> 3;
    int sl = blockIdx.x & 7;
    const float4* base = (const float4*)(x + (size_t)(sl * 8) * 32768 + c * 512);
    int t = threadIdx.x;
    float s = 0.f, q = 0.f;
#pragma unroll
    for (int j = 0; j < 4; j++) {
        int u = t + j * 256;
        int r = u >> 7, col = u & 127;
        float4 v = base[(size_t)r * 8192 + col];
        s += v.x + v.y + v.z + v.w;
        q += v.x * v.x + v.y * v.y + v.z * v.z + v.w * v.w;
    }
    __shared__ float rs[256], rq[256];
    rs[t] = s; rq[t] = q;
    __syncthreads();
    for (int st = 128; st > 0; st >>= 1) {
        if (t < st) { rs[t] += rs[t + st]; rq[t] += rq[t + st]; }
        __syncthreads();
    }
    if (t == 0) { atomicAdd(&g_bn0sum[c], rs[0]); atomicAdd(&g_bn0sq[c], rq[0]); }
}

// ---------------- parallel scan ----------------
__global__ void __launch_bounds__(1024) k_scanA() {
    __shared__ int wsum[32];
    int t = threadIdx.x;
    int n = blockIdx.x * 1024 + t;
    int lane = t & 31, w = t >> 5;
    int d = g_deg[n];
    int incl = d;
#pragma unroll
    for (int off = 1; off < 32; off <<= 1) {
        int v = __shfl_up_sync(0xffffffffu, incl, off);
        if (lane >= off) incl += v;
    }
    if (lane == 31) wsum[w] = incl;
    __syncthreads();
    if (w == 0) {
        int v = wsum[lane];
        int wi = v;
#pragma unroll
        for (int off = 1; off < 32; off <<= 1) {
            int u = __shfl_up_sync(0xffffffffu, wi, off);
            if (lane >= off) wi += u;
        }
        wsum[lane] = wi - v;
        if (lane == 31) g_bsum[blockIdx.x] = wi;
    }
    __syncthreads();
    g_rowptr[n] = incl - d + wsum[w];
}

__global__ void __launch_bounds__(1024) k_scanC() {
    __shared__ int boff;
    int t = threadIdx.x;
    if (t < 32) {
        int v = g_bsum[t];
        int s = v;
#pragma unroll
        for (int off = 1; off < 32; off <<= 1) {
            int u = __shfl_up_sync(0xffffffffu, s, off);
            if (t >= off) s += u;
        }
        if (t == (int)blockIdx.x) boff = s - v;
        if (t == 31 && blockIdx.x == 31) g_rowptr[NN] = s;
    }
    __syncthreads();
    int n = blockIdx.x * 1024 + t;
    int run = g_rowptr[n] + boff;
    g_rowptr[n] = run;
    g_cursor[n] = run + 1;
    g_csrc[run] = n;
}

__global__ void k_scatter(const int* __restrict__ ei) {
    int e = blockIdx.x * 1024 + threadIdx.x;
    if (e < EE) {
        int d = ei[EE + e];
        int pos = atomicAdd(&g_cursor[d], 1);
        g_csrc[pos] = ei[e];
    }
}

// ---------------- fuse W_l|W_r (fp16 K-major) + colsums + finalize BN0 ----------------
__global__ void k_fusew(const float* __restrict__ wl, const float* __restrict__ wr,
                        const float* __restrict__ g0, const float* __restrict__ b0) {
    int j = threadIdx.x;
    if (j < 64) {
        float m = g_bn0sum[j] * (1.f / 32768.f);
        float var = g_bn0sq[j] * (1.f / 32768.f) - m * m;
        float a = g0[j] * rsqrtf(var + EPSB);
        g_bn0s[j] = a;
        g_bn0t[j] = b0[j] - m * a;
    }
    float cs = 0.f;
    for (int c = 0; c < 64; c++) {
        float w = (j < 128) ? wl[c * 128 + j] : wr[c * 128 + (j - 128)];
        g_wfh[j * 64 + c] = __float2half_rn(w);
        cs += w;
    }
    g_wcs[j] = cs;
}

// ---------------- GEMM1 via HMMA ----------------
__global__ void __launch_bounds__(256, 1) k_gemm1h(const float* __restrict__ x) {
    extern __shared__ char sm[];
    uint32_t sb = smem_u32(sm);
    const uint32_t Ab = sb;
    const uint32_t Bb = sb + 16384;
    int tid = threadIdx.x;
    int blk = blockIdx.x;

#pragma unroll
    for (int it = 0; it < 8; it++) {
        int ch = tid + it * 256;
        int j = ch >> 3, c = ch & 7;
        cpa16(Bb + j * 128 + ((c * 16) ^ ((j & 7) * 16)), g_wfh + j * 64 + c * 8);
    }
    asm volatile("cp.async.commit_group;" ::: "memory");

    const float4* xg = (const float4*)(x + (size_t)blk * 128 * 64);
#pragma unroll
    for (int it = 0; it < 4; it++) {
        int ch = tid + it * 256;
        int r = ch >> 3, c = ch & 7;
        float4 f0 = xg[r * 16 + c * 2];
        float4 f1 = xg[r * 16 + c * 2 + 1];
        __half2 h0 = __float22half2_rn(make_float2(f0.x, f0.y));
        __half2 h1 = __float22half2_rn(make_float2(f0.z, f0.w));
        __half2 h2 = __float22half2_rn(make_float2(f1.x, f1.y));
        __half2 h3 = __float22half2_rn(make_float2(f1.z, f1.w));
        uint4 u;
        u.x = *(uint32_t*)&h0; u.y = *(uint32_t*)&h1;
        u.z = *(uint32_t*)&h2; u.w = *(uint32_t*)&h3;
        *(uint4*)(sm + r * 128 + ((c * 16) ^ ((r & 7) * 16))) = u;
    }
    asm volatile("cp.async.wait_group 0;" ::: "memory");
    __syncthreads();

    int lane = tid & 31, wid = tid >> 5;
    int wm = wid & 3;
    int wn = wid >> 2;
    float acc[2][16][4];
#pragma unroll
    for (int mt = 0; mt < 2; mt++)
#pragma unroll
        for (int nt = 0; nt < 16; nt++)
#pragma unroll
            for (int u = 0; u < 4; u++) acc[mt][nt][u] = 0.f;

    const int arow = wm * 32 + (lane & 15);
    const int aswz = (arow & 7) * 16;
    const int brow = wn * 128 + (lane & 15);
    const int bswz = (brow & 7) * 16;

#pragma unroll
    for (int k = 0; k < 4; k++) {
        const int c16 = k * 2 + (lane >> 4);
        uint32_t afr[2][4];
#pragma unroll
        for (int mt = 0; mt < 2; mt++)
            ldsm4(afr[mt], Ab + (arow + mt * 16) * 128 + ((c16 * 16) ^ aswz));
        uint32_t bfr[8][4];
#pragma unroll
        for (int n16 = 0; n16 < 8; n16++)
            ldsm4(bfr[n16], Bb + (brow + n16 * 16) * 128 + ((c16 * 16) ^ bswz));
#pragma unroll
        for (int mt = 0; mt < 2; mt++)
#pragma unroll
            for (int nt = 0; nt < 16; nt++) {
                const int n16 = nt >> 1, odd = nt & 1;
                mma16816h(acc[mt][nt], afr[mt], bfr[n16][odd], bfr[n16][odd + 2]);
            }
    }

    float* dst = (wn == 0) ? g_xl : g_xr;
#pragma unroll
    for (int mt = 0; mt < 2; mt++) {
        int row0 = blk * 128 + wm * 32 + mt * 16 + (lane >> 2);
        int row1 = row0 + 8;
        int cin0 = (row0 >> 3) & 63, cin1 = (row1 >> 3) & 63;
        float s0 = g_bn0s[cin0], t0 = g_bn0t[cin0];
        float s1 = g_bn0s[cin1], t1 = g_bn0t[cin1];
#pragma unroll
        for (int nt = 0; nt < 16; nt++) {
            int j = wn * 128 + nt * 8 + (lane & 3) * 2;
            float2 wc = *(const float2*)&g_wcs[j];
            int jj = j & 127;
            float2 v0, v1;
            v0.x = s0 * acc[mt][nt][0] + t0 * wc.x;
            v0.y = s0 * acc[mt][nt][1] + t0 * wc.y;
            v1.x = s1 * acc[mt][nt][2] + t1 * wc.x;
            v1.y = s1 * acc[mt][nt][3] + t1 * wc.y;
            *(float2*)&dst[(size_t)row0 * 128 + jj] = v0;
            *(float2*)&dst[(size_t)row1 * 128 + jj] = v1;
        }
    }
}

// ---------------- GATv2 gather (unroll x4) + fused BN1 stats ----------------
#define GAT_EDGE(AV) do { \
    float hx = AV.x + r.x; hx = fmaxf(hx, 0.2f * hx); \
    float hy = AV.y + r.y; hy = fmaxf(hy, 0.2f * hy); \
    float hz = AV.z + r.z; hz = fmaxf(hz, 0.2f * hz); \
    float hw = AV.w + r.w; hw = fmaxf(hw, 0.2f * hw); \
    float d = hx * av.x + hy * av.y + hz * av.z + hw * av.w; \
    d += __shfl_xor_sync(0xffffffffu, d, 8); \
    d += __shfl_xor_sync(0xffffffffu, d, 4); \
    d += __shfl_xor_sync(0xffffffffu, d, 2); \
    d += __shfl_xor_sync(0xffffffffu, d, 1); \
    float e = __expf(d); \
    z += e; \
    acc.x += e * AV.x; acc.y += e * AV.y; \
    acc.z += e * AV.z; acc.w += e * AV.w; \
} while (0)

__global__ void __launch_bounds__(256) k_gat(const float* __restrict__ att) {
    __shared__ float ssum[128], ssq[128];
    int tid = threadIdx.x;
    if (tid < 128) { ssum[tid] = 0.f; ssq[tid] = 0.f; }
    __syncthreads();
    int n = blockIdx.x * 8 + (tid >> 5);
    int lane = tid & 31;
    int row = g_rowptr[n];
    int end = g_rowptr[n + 1];
    float4 r = *(const float4*)(g_xr + (size_t)n * 128 + lane * 4);
    float4 av = *(const float4*)(att + lane * 4);
    float4 acc = make_float4(0.f, 0.f, 0.f, 0.f);
    float z = 0.f;
    for (int base = row; base < end; base += 32) {
        int m = end - base;
        if (m > 32) m = 32;
        int s = (lane < m) ? g_csrc[base + lane] : 0;
        int j = 0;
        for (; j + 4 <= m; j += 4) {
            int s0 = __shfl_sync(0xffffffffu, s, j);
            int s1 = __shfl_sync(0xffffffffu, s, j + 1);
            int s2 = __shfl_sync(0xffffffffu, s, j + 2);
            int s3 = __shfl_sync(0xffffffffu, s, j + 3);
            float4 a0 = *(const float4*)(g_xl + (size_t)s0 * 128 + lane * 4);
            float4 a1 = *(const float4*)(g_xl + (size_t)s1 * 128 + lane * 4);
            float4 a2 = *(const float4*)(g_xl + (size_t)s2 * 128 + lane * 4);
            float4 a3 = *(const float4*)(g_xl + (size_t)s3 * 128 + lane * 4);
            GAT_EDGE(a0);
            GAT_EDGE(a1);
            GAT_EDGE(a2);
            GAT_EDGE(a3);
        }
        for (; j < m; j++) {
            int s0 = __shfl_sync(0xffffffffu, s, j);
            float4 a0 = *(const float4*)(g_xl + (size_t)s0 * 128 + lane * 4);
            GAT_EDGE(a0);
        }
    }
    float inv = 1.f / z;
    float4 o = make_float4(acc.x * inv, acc.y * inv, acc.z * inv, acc.w * inv);
    *(float4*)(g_gacc + (size_t)n * 128 + lane * 4) = o;
    atomicAdd(&ssum[lane * 4 + 0], o.x);
    atomicAdd(&ssum[lane * 4 + 1], o.y);
    atomicAdd(&ssum[lane * 4 + 2], o.z);
    atomicAdd(&ssum[lane * 4 + 3], o.w);
    atomicAdd(&ssq[lane * 4 + 0], o.x * o.x);
    atomicAdd(&ssq[lane * 4 + 1], o.y * o.y);
    atomicAdd(&ssq[lane * 4 + 2], o.z * o.z);
    atomicAdd(&ssq[lane * 4 + 3], o.w * o.w);
    __syncthreads();
    if (tid < 128) {
        atomicAdd(&g_bn1sum[tid], ssum[tid]);
        atomicAdd(&g_bn1sq[tid], ssq[tid]);
    }
}

// ---------------- fused: relu(BN1) -> out + fp16 (inline coefficients) ----------------
__global__ void __launch_bounds__(1024) k_xn1s(float* __restrict__ out,
                                               const float* __restrict__ g1,
                                               const float* __restrict__ b1) {
    __shared__ float sa[128], sc[128];
    int tid = threadIdx.x;
    if (tid < 128) {
        float m = g_bn1sum[tid] * (1.f / 32768.f);
        float var = g_bn1sq[tid] * (1.f / 32768.f) - m * m;
        float a = g1[tid] * rsqrtf(var + EPSB);
        sa[tid] = a;
        sc[tid] = b1[tid] - m * a;
    }
    __syncthreads();
    int i = blockIdx.x * 1024 + tid;
    int j = tid & 127;
    float v = g_gacc[i] * sa[j] + sc[j];
    v = fmaxf(v, 0.f);
    out[i] = v;
    g_xh[i] = __float2half_rn(v);
}

// ---------------- conv weight fp16 ----------------
__global__ void k_whalf(const float* __restrict__ w) {
    int idx = blockIdx.x * 256 + threadIdx.x;   // [k][o][i]
    int i = idx & 511;
    int o = (idx >> 9) & 511;
    int k = idx >> 18;
    g_wh[idx] = __float2half_rn(w[(o * 512 + i) * 9 + k]);
}

// ---------------- conv via mma.sync fp16: 4-stage W pipeline, 1 sync/iter ----------------
#define W_STAGE 16384
#define X_BASE  65536
#define X_BUF   34816

__device__ __forceinline__ void fillW(uint32_t sb, int st, int t, int o0, int tid) {
    int kk = t % 9;
    int i0 = (t / 9) * 64;
#pragma unroll
    for (int j = 0; j < 4; j++) {
        int ch = tid + j * 256;
        int r = ch >> 3;
        int c = ch & 7;
        uint32_t dst = sb + st * W_STAGE + r * 128 + ((c * 16) ^ ((r & 7) * 16));
        const __half* src = g_wh + (size_t)(kk * 512 + o0 + r) * 512 + i0 + c * 8;
        cpa16(dst, src);
    }
}

__device__ __forceinline__ void fillX(char* cs, uint32_t sb, int jch, int b0, int tid) {
    int buf = jch & 1;
    int i0 = jch * 64;
#pragma unroll
    for (int jj = 0; jj < 9; jj++) {
        int ch = tid + jj * 256;
        if (ch < 2176) {
            int h = (ch >= 1088) ? 1 : 0;
            int ca = ch - h * 1088;
            int r = ca >> 3;
            int c = ca & 7;
            uint32_t rel = X_BASE + buf * X_BUF + h * 17408 + r * 128 + ((c * 16) ^ ((r & 7) * 16));
            int q = r - 4;
            if ((unsigned)q < 128u) {
                const __half* src = g_xh + (size_t)((b0 + h) * 128 + q) * 512 + i0 + c * 8;
                cpa16(sb + rel, src);
            } else {
                *(uint4*)(cs + rel) = make_uint4(0u, 0u, 0u, 0u);
            }
        }
    }
}

__global__ void __launch_bounds__(256, 1) k_conv_hmma() {
    extern __shared__ char cs[];
    uint32_t sb = smem_u32(cs);
    const int tid = threadIdx.x;
    const int lane = tid & 31;
    const int wid = tid >> 5;
    const int wm = wid & 3;
    const int wn = wid >> 2;
    const int b0 = blockIdx.x * 2;
    const int o0 = blockIdx.y * 128;

    float acc[2][16][4];
#pragma unroll
    for (int mt = 0; mt < 2; mt++)
#pragma unroll
        for (int nt = 0; nt < 16; nt++)
#pragma unroll
            for (int u = 0; u < 4; u++) acc[mt][nt][u] = 0.f;

    fillW(sb, 0, 0, o0, tid);
    fillX(cs, sb, 0, b0, tid);
    asm volatile("cp.async.commit_group;" ::: "memory");
    fillW(sb, 1, 1, o0, tid);
    asm volatile("cp.async.commit_group;" ::: "memory");
    fillW(sb, 2, 2, o0, tid);
    asm volatile("cp.async.commit_group;" ::: "memory");

    const int arow = wm * 32 + (lane & 15);
    const int aswz = (arow & 7) * 16;
    const int brow0 = lane & 15;

    for (int t = 0; t < 72; t++) {
        if (t < 70)       asm volatile("cp.async.wait_group 2;" ::: "memory");
        else if (t == 70) asm volatile("cp.async.wait_group 1;" ::: "memory");
        else              asm volatile("cp.async.wait_group 0;" ::: "memory");
        __syncthreads();

        const int st = t & 3;                // 4 W stages
        const int kk = t % 9;
        const int xb = (t / 9) & 1;
        const uint32_t wbase = sb + st * W_STAGE;
        const uint32_t xbase = sb + X_BASE + xb * X_BUF + wn * 17408;
        const int brow = brow0 + kk;
        const int bswz = (brow & 7) * 16;

#pragma unroll
        for (int s = 0; s < 4; s++) {
            const int c16 = s * 2 + (lane >> 4);
            uint32_t afr[2][4];
#pragma unroll
            for (int mt = 0; mt < 2; mt++) {
                uint32_t addr = wbase + mt * 2048 + arow * 128 + ((c16 * 16) ^ aswz);
                ldsm4(afr[mt], addr);
            }
            uint32_t bfr[8][4];
#pragma unroll
            for (int n16 = 0; n16 < 8; n16++) {
                uint32_t addr = xbase + (brow + n16 * 16) * 128 + ((c16 * 16) ^ bswz);
                ldsm4(bfr[n16], addr);
            }
#pragma unroll
            for (int mt = 0; mt < 2; mt++)
#pragma unroll
                for (int nt = 0; nt < 16; nt++) {
                    const int n16 = nt >> 1, odd = nt & 1;
                    mma16816h(acc[mt][nt], afr[mt], bfr[n16][odd], bfr[n16][odd + 2]);
                }
        }
        // no second sync: refill targets stage (t+3)&3 != t&3 and the
        // opposite X buffer; start-of-iteration sync covers prior readers.
        const int tf = t + 3;
        if (tf < 72) {
            fillW(sb, tf & 3, tf, o0, tid);
            if (tf % 9 == 0) fillX(cs, sb, tf / 9, b0, tid);
            asm volatile("cp.async.commit_group;" ::: "memory");
        }
    }

    const int b = b0 + wn;
#pragma unroll
    for (int mt = 0; mt < 2; mt++) {
        float slo = 0.f, qlo = 0.f, shi = 0.f, qhi = 0.f;
#pragma unroll
        for (int nt = 0; nt < 16; nt++) {
            int o = o0 + wm * 32 + mt * 16 + (lane >> 2);
            int p = nt * 8 + (lane & 3) * 2;
            float2 v0 = make_float2(acc[mt][nt][0], acc[mt][nt][1]);
            float2 v1 = make_float2(acc[mt][nt][2], acc[mt][nt][3]);
            *(float2*)&g_y[((size_t)b * 512 + o) * 128 + p] = v0;
            *(float2*)&g_y[((size_t)b * 512 + o + 8) * 128 + p] = v1;
            slo += v0.x + v0.y; qlo += v0.x * v0.x + v0.y * v0.y;
            shi += v1.x + v1.y; qhi += v1.x * v1.x + v1.y * v1.y;
        }
#pragma unroll
        for (int m = 1; m <= 2; m <<= 1) {
            slo += __shfl_xor_sync(0xffffffffu, slo, m);
            qlo += __shfl_xor_sync(0xffffffffu, qlo, m);
            shi += __shfl_xor_sync(0xffffffffu, shi, m);
            qhi += __shfl_xor_sync(0xffffffffu, qhi, m);
        }
        if ((lane & 3) == 0) {
            int o = o0 + wm * 32 + mt * 16 + (lane >> 2);
            atomicAdd(&g_bn2sum[o], slo);
            atomicAdd(&g_bn2sq[o], qlo);
            atomicAdd(&g_bn2sum[o + 8], shi);
            atomicAdd(&g_bn2sq[o + 8], qhi);
        }
    }
}

// ---------------- final (inline BN2 coefficients) ----------------
__global__ void k_final(float* __restrict__ out,
                        const float* __restrict__ g2, const float* __restrict__ b2) {
    __shared__ float sh[32][33];
    __shared__ float sa[32], sc[32];
    int bb = blockIdx.z;
    int o0 = blockIdx.y * 32;
    int p0 = blockIdx.x * 32;
    int tid = threadIdx.x;
    if (tid < 32) {
        int o = o0 + tid;
        float m = g_bn2sum[o] * (1.f / 8192.f);
        float var = g_bn2sq[o] * (1.f / 8192.f) - m * m;
        float a = g2[o] * rsqrtf(var + EPSB);
        sa[tid] = a;
        sc[tid] = b2[o] - m * a;
    }
    __syncthreads();
    for (int t = tid; t < 1024; t += 256) {
        int r = t >> 5, c = t & 31;
        int o = o0 + r;
        float v = g_y[(bb * 512 + o) * 128 + p0 + c];
        v = v * sa[r] + sc[r];
        sh[r][c] = fmaxf(v, 0.f);
    }
    __syncthreads();
    for (int t = tid; t < 1024; t += 256) {
        int r = t >> 5, c = t & 31;
        int d = p0 + r, tt = o0 + c;
        int idx = bb * 65536 + d * 512 + tt;
        out[idx] += sh[c][r];
    }
}

// ---------------- launch ----------------
extern "C" void kernel_launch(void* const* d_in, const int* in_sizes, int n_in,
                              void* d_out, int out_size) {
    const float* x     = (const float*)d_in[0];
    const int*   ei    = (const int*)d_in[1];
    const float* bn0g  = (const float*)d_in[2];
    const float* bn0b  = (const float*)d_in[3];
    const float* wl    = (const float*)d_in[4];
    const float* wr    = (const float*)d_in[5];
    const float* att   = (const float*)d_in[6];
    const float* bn1g  = (const float*)d_in[8];
    const float* bn1b  = (const float*)d_in[9];
    const float* convw = (const float*)d_in[10];
    const float* bn2g  = (const float*)d_in[12];
    const float* bn2b  = (const float*)d_in[13];
    float* out = (float*)d_out;

    cudaFuncSetAttribute(k_gemm1h, cudaFuncAttributeMaxDynamicSharedMemorySize, 49152);
    cudaFuncSetAttribute(k_conv_hmma, cudaFuncAttributeMaxDynamicSharedMemorySize, 135168);

    // fork: side stream s1 runs the feature track
    cudaEventRecord(g_hx.ev0, 0);
    cudaStreamWaitEvent(g_hx.s1, g_hx.ev0, 0);

    // branch B (s1)
    k_initB<<<1, 1024, 0, g_hx.s1>>>();
    k_bn0p<<<512, 256, 0, g_hx.s1>>>(x);
    k_fusew<<<1, 256, 0, g_hx.s1>>>(wl, wr, bn0g, bn0b);
    k_gemm1h<<<256, 256, 49152, g_hx.s1>>>(x);
    cudaEventRecord(g_hx.ev1, g_hx.s1);
    k_whalf<<<9216, 256, 0, g_hx.s1>>>(convw);
    cudaEventRecord(g_hx.ev2, g_hx.s1);

    // branch A (capture stream): CSR build
    k_initA<<<32, 1024>>>();
    k_hist<<<512, 1024>>>(ei);
    k_scanA<<<32, 1024>>>();
    k_scanC<<<32, 1024>>>();
    k_scatter<<<512, 1024>>>(ei);

    // join 1: gat needs gemm1 (xl/xr) + scatter (csrc)
    cudaStreamWaitEvent(0, g_hx.ev1, 0);
    k_gat<<<4096, 256>>>(att);
    k_xn1s<<<4096, 1024>>>(out, bn1g, bn1b);

    // join 2: conv needs whalf (g_wh) + xn1s (g_xh)
    cudaStreamWaitEvent(0, g_hx.ev2, 0);
    k_conv_hmma<<<dim3(32, 4), 256, 135168>>>();
    k_final<<<dim3(4, 16, 64), 256>>>(out, bn2g, bn2b);
}